// round 1
// baseline (speedup 1.0000x reference)
#include <cuda_runtime.h>
#include <cstdint>

// TurboQuantValue: per-row (128 elems) 4-bit min/max quantize + dequantize.
// out[i] = clip(rint((x[i]-vmin)/(vscale+1e-10)),0,15)*vscale + vmin
// vscale = (vmax-vmin)/(15+1e-10)
//
// One warp per row; lane l owns elements [4l, 4l+4) as a float4.
// Memory-bound: 256MB in + 256MB out.

#define WARPS_PER_BLOCK 8
#define THREADS (WARPS_PER_BLOCK * 32)

__global__ __launch_bounds__(THREADS)
void turboquant_kernel(const float4* __restrict__ in,
                       float4* __restrict__ out,
                       int n_rows)
{
    int warp_in_block = threadIdx.x >> 5;
    int lane = threadIdx.x & 31;
    int row = blockIdx.x * WARPS_PER_BLOCK + warp_in_block;
    if (row >= n_rows) return;

    // 128 floats per row = 32 float4; lane -> one float4
    size_t idx = (size_t)row * 32 + lane;
    float4 a = in[idx];

    // local min/max over 4 elements
    float mn = fminf(fminf(a.x, a.y), fminf(a.z, a.w));
    float mx = fmaxf(fmaxf(a.x, a.y), fmaxf(a.z, a.w));

    // warp reduction (full warp active: row covers exactly 32 lanes)
    #pragma unroll
    for (int off = 16; off > 0; off >>= 1) {
        mn = fminf(mn, __shfl_xor_sync(0xFFFFFFFFu, mn, off));
        mx = fmaxf(mx, __shfl_xor_sync(0xFFFFFFFFu, mx, off));
    }

    // scale & reciprocal (IEEE rn division, once per row per lane — cheap)
    float vscale = (mx - mn) / (15.0f + 1e-10f);
    float denom  = vscale + 1e-10f;
    float inv    = 1.0f / denom;           // IEEE div; amortized over 128 elems
    float nb     = -mn * inv;              // so (x-mn)*inv == fma(x, inv, nb) up to 1 ulp

    float4 r;
    {
        float q;
        q = fminf(fmaxf(rintf(fmaf(a.x, inv, nb)), 0.0f), 15.0f);
        r.x = fmaf(q, vscale, mn);
        q = fminf(fmaxf(rintf(fmaf(a.y, inv, nb)), 0.0f), 15.0f);
        r.y = fmaf(q, vscale, mn);
        q = fminf(fmaxf(rintf(fmaf(a.z, inv, nb)), 0.0f), 15.0f);
        r.z = fmaf(q, vscale, mn);
        q = fminf(fmaxf(rintf(fmaf(a.w, inv, nb)), 0.0f), 15.0f);
        r.w = fmaf(q, vscale, mn);
    }

    out[idx] = r;
}

extern "C" void kernel_launch(void* const* d_in, const int* in_sizes, int n_in,
                              void* d_out, int out_size)
{
    const float4* x = (const float4*)d_in[0];
    float4* out = (float4*)d_out;

    int n_elems = in_sizes[0];          // 67,108,864
    int n_rows = n_elems / 128;         // 524,288

    int blocks = (n_rows + WARPS_PER_BLOCK - 1) / WARPS_PER_BLOCK;
    turboquant_kernel<<<blocks, THREADS>>>(x, out, n_rows);
}

// round 2
// speedup vs baseline: 1.0655x; 1.0655x over previous
#include <cuda_runtime.h>
#include <cstdint>

// TurboQuantValue: per-row (128 elems) 4-bit min/max quantize + dequantize.
// out[i] = clip(rint((x[i]-vmin)/(vscale+1e-10)),0,15)*vscale + vmin
// vscale = (vmax-vmin)/(15+1e-10)
//
// One warp handles TWO rows (2x float4 per thread -> MLP=2).
// min/max via REDUX.SYNC on order-preserving uint keys (no shfl tree).
// Memory-bound: 256MB in + 256MB out.

#define WARPS_PER_BLOCK 8
#define ROWS_PER_WARP 2
#define THREADS (WARPS_PER_BLOCK * 32)

// Order-preserving float<->uint key: key ascending <=> float ascending.
__device__ __forceinline__ unsigned f2key(float f) {
    unsigned u = __float_as_uint(f);
    return u ^ ((unsigned)((int)u >> 31) | 0x80000000u);
}
__device__ __forceinline__ float key2f(unsigned k) {
    unsigned u = (k & 0x80000000u) ? (k ^ 0x80000000u) : ~k;
    return __uint_as_float(u);
}

__device__ __forceinline__ float4 quant_row(float4 a) {
    // local min/max over this thread's 4 elements
    float mn = fminf(fminf(a.x, a.y), fminf(a.z, a.w));
    float mx = fmaxf(fmaxf(a.x, a.y), fmaxf(a.z, a.w));

    // warp-wide min/max via redux.sync on monotone keys
    unsigned kmn = __reduce_min_sync(0xFFFFFFFFu, f2key(mn));
    unsigned kmx = __reduce_max_sync(0xFFFFFFFFu, f2key(mx));
    mn = key2f(kmn);
    mx = key2f(kmx);

    float vscale = (mx - mn) / (15.0f + 1e-10f);
    float inv    = 1.0f / (vscale + 1e-10f);   // one IEEE div per row per lane
    float nb     = -mn * inv;

    float4 r;
    float q;
    q = fminf(fmaxf(rintf(fmaf(a.x, inv, nb)), 0.0f), 15.0f);
    r.x = fmaf(q, vscale, mn);
    q = fminf(fmaxf(rintf(fmaf(a.y, inv, nb)), 0.0f), 15.0f);
    r.y = fmaf(q, vscale, mn);
    q = fminf(fmaxf(rintf(fmaf(a.z, inv, nb)), 0.0f), 15.0f);
    r.z = fmaf(q, vscale, mn);
    q = fminf(fmaxf(rintf(fmaf(a.w, inv, nb)), 0.0f), 15.0f);
    r.w = fmaf(q, vscale, mn);
    return r;
}

__global__ __launch_bounds__(THREADS)
void turboquant_kernel(const float4* __restrict__ in,
                       float4* __restrict__ out,
                       int n_rows)
{
    int warp_in_block = threadIdx.x >> 5;
    int lane = threadIdx.x & 31;
    int row0 = (blockIdx.x * WARPS_PER_BLOCK + warp_in_block) * ROWS_PER_WARP;
    if (row0 >= n_rows) return;

    // 128 floats per row = 32 float4; lane -> one float4 per row
    size_t idx0 = (size_t)row0 * 32 + lane;

    // front-load both rows (independent LDG.128s, MLP=2)
    float4 a = in[idx0];
    float4 b = in[idx0 + 32];

    float4 ra = quant_row(a);
    float4 rb = quant_row(b);

    out[idx0]      = ra;
    out[idx0 + 32] = rb;
}

extern "C" void kernel_launch(void* const* d_in, const int* in_sizes, int n_in,
                              void* d_out, int out_size)
{
    const float4* x = (const float4*)d_in[0];
    float4* out = (float4*)d_out;

    int n_elems = in_sizes[0];          // 67,108,864
    int n_rows = n_elems / 128;         // 524,288

    int rows_per_block = WARPS_PER_BLOCK * ROWS_PER_WARP;
    int blocks = (n_rows + rows_per_block - 1) / rows_per_block;
    turboquant_kernel<<<blocks, THREADS>>>(x, out, n_rows);
}